// round 1
// baseline (speedup 1.0000x reference)
#include <cuda_runtime.h>
#include <math.h>

// ---------------- static problem config ----------------
#define Bq    8
#define Pp    8
#define Nn    100
#define Dm    256
#define Hh    8
#define DKk   32
#define Mm    64
#define Kg    16
#define Ll    800            // P*N
#define BL    6400           // B*L
#define NSPLIT 25
#define KCHUNK 400           // 25*400 = 10000

// scale: s * DK^{-0.25} = 2 * 32^{-0.25}
#define PHI_SCALE 0.84089641525f

// ---------------- scratch (device globals; no allocation) ----------------
__device__ __align__(16) float g_q   [BL*Dm];
__device__ __align__(16) float g_k   [BL*Dm];
__device__ __align__(16) float g_v   [BL*Dm];
__device__ __align__(16) float g_qp  [BL*Hh*Mm];
__device__ __align__(16) float g_kdd [BL*Hh*Mm];
__device__              float g_kdiag[BL*Hh];
__device__              float g_krmax[BL*Hh];
__device__              float g_kmax [Bq*Hh];
__device__ __align__(16) float g_kp  [BL*Hh*Mm];
__device__ __align__(16) float g_kvs [Bq*Hh*Kg*Mm*DKk];
__device__ __align__(16) float g_ksum[Bq*Hh*Kg*Mm];
__device__ __align__(16) float g_z   [BL*Dm];
__device__ __align__(16) float g_h1p [NSPLIT*512*128];
__device__              float g_wpat [512];
__device__ __align__(16) float g_fused[Bq*Pp*Nn*Nn];
__device__              float g_rden [Bq*Pp*Nn];

// ---------------- generic SGEMM: C = A[M,K] @ W[N,K]^T (+bias) ----------------
// 64x64 tile, BK=16, 256 threads, 4x4 micro-tile. grid.z = split-K partials
// (writes to C + z*Mr*Nc when gridDim.z > 1; bias applied only when non-null).
__global__ void sgemm_nt(const float* __restrict__ A, const float* __restrict__ W,
                         const float* __restrict__ bias, float* __restrict__ C,
                         int Mr, int Nc, int Kd, int klen)
{
    __shared__ float As[16][65];
    __shared__ float Ws[16][65];
    int tid  = threadIdx.x;
    int tx   = tid & 15, ty = tid >> 4;
    int row0 = blockIdx.x * 64, col0 = blockIdx.y * 64;
    int k0   = blockIdx.z * klen;
    float* Cp = C + (size_t)blockIdx.z * (size_t)Mr * Nc;

    float acc[4][4];
#pragma unroll
    for (int i = 0; i < 4; i++)
#pragma unroll
        for (int j = 0; j < 4; j++) acc[i][j] = 0.f;

    int r  = tid >> 2;
    int c4 = (tid & 3) * 4;

    for (int kk = k0; kk < k0 + klen; kk += 16) {
        float4 a4 = *(const float4*)&A[(size_t)(row0 + r) * Kd + kk + c4];
        As[c4+0][r] = a4.x; As[c4+1][r] = a4.y; As[c4+2][r] = a4.z; As[c4+3][r] = a4.w;
        float4 w4 = *(const float4*)&W[(size_t)(col0 + r) * Kd + kk + c4];
        Ws[c4+0][r] = w4.x; Ws[c4+1][r] = w4.y; Ws[c4+2][r] = w4.z; Ws[c4+3][r] = w4.w;
        __syncthreads();
#pragma unroll
        for (int c = 0; c < 16; c++) {
            float a[4], w[4];
#pragma unroll
            for (int i = 0; i < 4; i++) { a[i] = As[c][ty*4+i]; w[i] = Ws[c][tx*4+i]; }
#pragma unroll
            for (int i = 0; i < 4; i++)
#pragma unroll
                for (int j = 0; j < 4; j++) acc[i][j] += a[i] * w[j];
        }
        __syncthreads();
    }

#pragma unroll
    for (int i = 0; i < 4; i++) {
        int rr = row0 + ty*4 + i;
#pragma unroll
        for (int j = 0; j < 4; j++) {
            int cc  = col0 + tx*4 + j;
            float v = acc[i][j];
            if (bias) v += bias[cc];
            Cp[(size_t)rr * Nc + cc] = v;
        }
    }
}

// ---------------- Performer feature map ----------------
// one block (64 threads) per (b,l,h) unit. is_query: finalize phi with
// per-unit stabilizer. else: stash dd/diag/rowmax for the global-key pass.
__global__ void phi_kernel(const float* __restrict__ din, const float* __restrict__ proj,
                           float* __restrict__ outphi, float* __restrict__ dd_out,
                           float* __restrict__ diag_out, float* __restrict__ rmax_out,
                           int is_query)
{
    int u = blockIdx.x;
    int m = threadIdx.x;
    __shared__ float data[32];
    __shared__ float red[64];
    if (m < 32) data[m] = din[(size_t)u*32 + m] * PHI_SCALE;
    __syncthreads();
    float dd = 0.f, diag = 0.f;
#pragma unroll
    for (int d2 = 0; d2 < 32; d2++) {
        float x = data[d2];
        dd  += x * proj[m*32 + d2];
        diag += x * x;
    }
    diag *= 0.5f;
    red[m] = dd;
    __syncthreads();
#pragma unroll
    for (int s = 32; s > 0; s >>= 1) {
        if (m < s) red[m] = fmaxf(red[m], red[m + s]);
        __syncthreads();
    }
    if (is_query) {
        outphi[(size_t)u*64 + m] = 0.125f * (expf(dd - diag - red[0]) + 1e-6f);
    } else {
        dd_out[(size_t)u*64 + m] = dd;
        if (m == 0) { diag_out[u] = diag; rmax_out[u] = red[0]; }
    }
}

// key stabilizer: max over tokens per (b,h)
__global__ void kmax_kernel(const float* __restrict__ rmax, float* __restrict__ kmax)
{
    int bh = blockIdx.x; int b = bh >> 3, h = bh & 7;
    int t = threadIdx.x;
    __shared__ float red[256];
    float mx = -1e30f;
    for (int l = t; l < Ll; l += 256) mx = fmaxf(mx, rmax[(b*Ll + l)*Hh + h]);
    red[t] = mx; __syncthreads();
    for (int s = 128; s > 0; s >>= 1) { if (t < s) red[t] = fmaxf(red[t], red[t+s]); __syncthreads(); }
    if (t == 0) kmax[bh] = red[0];
}

__global__ void kp2_kernel(const float* __restrict__ dd, const float* __restrict__ diag,
                           const float* __restrict__ kmax, float* __restrict__ kp)
{
    int i = blockIdx.x * 256 + threadIdx.x;   // < BL*H*M
    int u = i >> 6;
    int b = u / (Ll * Hh);
    int h = u & 7;
    kp[i] = 0.125f * (expf(dd[i] - diag[u] - kmax[b*Hh + h]) + 1e-6f);
}

// ---------------- kvs + ksum: contract over L ----------------
// block per (b,h,k). 256 threads: thread = (mrow = t>>5, d = t&31), holds 8 m-values.
__global__ void kvs_kernel(const float* __restrict__ kp, const float* __restrict__ v,
                           const float* __restrict__ gum,
                           float* __restrict__ kvs, float* __restrict__ ksum)
{
    int bhk = blockIdx.x;
    int k = bhk & 15, h = (bhk >> 4) & 7, b = bhk >> 7;
    int t = threadIdx.x;
    int d = t & 31, mr = t >> 5;
    __shared__ float kp_s[8][64];
    __shared__ float v_s[8][32];
    __shared__ float e_s[8];
    float acc[8];
#pragma unroll
    for (int j = 0; j < 8; j++) acc[j] = 0.f;
    float s = 0.f;

    for (int l0 = 0; l0 < Ll; l0 += 8) {
        for (int idx = t; idx < 512; idx += 256) {
            int c = idx >> 6, m = idx & 63;
            kp_s[c][m] = kp[((size_t)((b*Ll + l0 + c)*Hh + h) << 6) + m];
        }
        { int c = t >> 5; v_s[c][d] = v[(size_t)(b*Ll + l0 + c)*Dm + h*32 + d]; }
        if (t < 8) e_s[t] = expf(gum[(((b*Ll + l0 + t)*Hh + h) << 4) + k]);
        __syncthreads();
#pragma unroll
        for (int c = 0; c < 8; c++) {
            float ve = v_s[c][d] * e_s[c];
#pragma unroll
            for (int j = 0; j < 8; j++) acc[j] += kp_s[c][mr + 8*j] * ve;
        }
        if (t < 64) {
#pragma unroll
            for (int c = 0; c < 8; c++) s += kp_s[c][t] * e_s[c];
        }
        __syncthreads();
    }
    size_t base = (size_t)bhk * 64 * 32;
#pragma unroll
    for (int j = 0; j < 8; j++) kvs[base + (size_t)(mr + 8*j)*32 + d] = acc[j];
    if (t < 64) ksum[(size_t)bhk*64 + t] = s;
}

// ---------------- z = mean_k (qp @ kvs[k]) / (qp @ ksum[k]) ----------------
// grid (B*H, 16 chunks of 50 tokens). 512 threads = (k = t>>5, d = t&31).
// each thread caches kvs[b,h,k,:,d] (64 floats) in registers for the whole chunk.
__global__ void z_kernel(const float* __restrict__ qp, const float* __restrict__ kvs,
                         const float* __restrict__ ksum, float* __restrict__ z)
{
    int bh = blockIdx.x; int b = bh >> 3, h = bh & 7;
    int l0 = blockIdx.y * 50;
    int t = threadIdx.x;
    int d = t & 31, k = t >> 5, lane = d;
    __shared__ float qp_s[64];
    __shared__ float ks_s[16*64];
    __shared__ float sred[512];

    float kv[64];
#pragma unroll
    for (int m = 0; m < 64; m++)
        kv[m] = kvs[((size_t)(bh*16 + k)*64 + m)*32 + d];
    for (int i = t; i < 1024; i += 512) ks_s[i] = ksum[(size_t)bh*1024 + i];
    __syncthreads();

    for (int li = 0; li < 50; li++) {
        int l = l0 + li;
        int u = (b*Ll + l)*Hh + h;
        if (t < 64) qp_s[t] = qp[(size_t)u*64 + t];
        __syncthreads();
        float den = qp_s[lane]    * ks_s[k*64 + lane]
                  + qp_s[lane+32] * ks_s[k*64 + lane + 32];
#pragma unroll
        for (int o = 16; o > 0; o >>= 1) den += __shfl_xor_sync(0xffffffffu, den, o);
        den += 1e-8f;
        float num = 0.f;
#pragma unroll
        for (int m = 0; m < 64; m++) num += qp_s[m] * kv[m];
        sred[t] = num / (den * 16.0f);
        __syncthreads();
        if (t < 32) {
            float ss = 0.f;
#pragma unroll
            for (int kk = 0; kk < 16; kk++) ss += sred[kk*32 + t];
            z[(size_t)(b*Ll + l)*Dm + h*32 + t] = ss;
        }
        __syncthreads();
    }
}

// ---------------- LayerNorm over DK per (b,l,h), in-place ----------------
__global__ void ln_kernel(float* __restrict__ z, const float* __restrict__ g,
                          const float* __restrict__ bb)
{
    int w = threadIdx.x >> 5, lane = threadIdx.x & 31;
    int u = blockIdx.x * 8 + w;                 // < BL*H
    float x = z[(size_t)u*32 + lane];
    float mu = x;
#pragma unroll
    for (int o = 16; o > 0; o >>= 1) mu += __shfl_xor_sync(0xffffffffu, mu, o);
    mu *= (1.0f / 32.0f);
    float df = x - mu;
    float v2 = df * df;
#pragma unroll
    for (int o = 16; o > 0; o >>= 1) v2 += __shfl_xor_sync(0xffffffffu, v2, o);
    float var = v2 * (1.0f / 32.0f);
    z[(size_t)u*32 + lane] = df * rsqrtf(var + 1e-5f) * g[lane] + bb[lane];
}

// ---------------- patch score + softmax over patch dim ----------------
// reduces split-K partials of h1, relu, dot with out_w, softmax over 8.
__global__ void score_kernel(const float* __restrict__ h1p, const float* __restrict__ fc_b,
                             const float* __restrict__ out_w, const float* __restrict__ out_b,
                             float* __restrict__ wout)
{
    int bp = blockIdx.x;                        // < 64
    int t = threadIdx.x >> 5, lane = threadIdx.x & 31;
    __shared__ float sc[8];
    float p = 0.f;
    for (int j = lane; j < 128; j += 32) {
        float hv = fc_b[j];
        for (int s = 0; s < NSPLIT; s++) hv += h1p[(size_t)s*65536 + (bp*8 + t)*128 + j];
        hv = fmaxf(hv, 0.f);
        p += hv * out_w[j];
    }
#pragma unroll
    for (int o = 16; o > 0; o >>= 1) p += __shfl_xor_sync(0xffffffffu, p, o);
    if (lane == 0) sc[t] = p + out_b[0];
    __syncthreads();
    if (threadIdx.x == 0) {
        float mx = sc[0];
#pragma unroll
        for (int i = 1; i < 8; i++) mx = fmaxf(mx, sc[i]);
        float e[8], sum = 0.f;
#pragma unroll
        for (int i = 0; i < 8; i++) { e[i] = expf(sc[i] - mx); sum += e[i]; }
#pragma unroll
        for (int i = 0; i < 8; i++) wout[bp*8 + i] = e[i] / sum;
    }
}

// fused[b,p,i,j] = sum_t adj[b, p*8+t, i, j] * w[bp,t]
__global__ void fused_kernel(const float* __restrict__ adj, const float* __restrict__ wpat,
                             float* __restrict__ fused)
{
    int idx = blockIdx.x * 256 + threadIdx.x;   // < 640000
    int bp = idx / 10000;
    int rem = idx - bp * 10000;
    float s = 0.f;
#pragma unroll
    for (int t = 0; t < 8; t++) s += adj[(size_t)(bp*8 + t)*10000 + rem] * wpat[bp*8 + t];
    fused[idx] = s;
}

// row L1 norm denominators
__global__ void rden_kernel(const float* __restrict__ fused, float* __restrict__ rden)
{
    int w = threadIdx.x >> 5, lane = threadIdx.x & 31;
    int row = blockIdx.x * 8 + w;               // < 6400
    float s = 0.f;
    for (int j = lane; j < 100; j += 32) s += fabsf(fused[(size_t)row*100 + j]);
#pragma unroll
    for (int o = 16; o > 0; o >>= 1) s += __shfl_xor_sync(0xffffffffu, s, o);
    if (lane == 0) rden[row] = fmaxf(s, 1e-12f);
}

// relational bias: z += (fused/rden) @ V  per (b,p) block-diagonal
__global__ void biasadd_kernel(const float* __restrict__ fused, const float* __restrict__ rden,
                               const float* __restrict__ v, float* __restrict__ z)
{
    __shared__ float A_s[100][101];
    int blk = blockIdx.x;                       // b*8+p
    int t = threadIdx.x;                        // 256 -> column d of the 256-wide V
    for (int idx = t; idx < 10000; idx += 256) {
        int i = idx / 100, j = idx - i * 100;
        A_s[i][j] = fused[(size_t)blk*10000 + idx] / rden[blk*100 + i];
    }
    __syncthreads();
    int base = blk * 100;                       // b*800 + p*100 == (b*8+p)*100
    for (int i0 = 0; i0 < 100; i0 += 20) {
        float acc[20];
#pragma unroll
        for (int ii = 0; ii < 20; ii++) acc[ii] = 0.f;
        for (int j = 0; j < 100; j++) {
            float vj = v[(size_t)(base + j)*256 + t];
#pragma unroll
            for (int ii = 0; ii < 20; ii++) acc[ii] += A_s[i0 + ii][j] * vj;
        }
#pragma unroll
        for (int ii = 0; ii < 20; ii++)
            z[(size_t)(base + i0 + ii)*256 + t] += acc[ii];
    }
}

// ---------------- launcher ----------------
extern "C" void kernel_launch(void* const* d_in, const int* in_sizes, int n_in,
                              void* d_out, int out_size)
{
    const float* x     = (const float*)d_in[0];
    const float* adj   = (const float*)d_in[1];
    const float* Wq_w  = (const float*)d_in[2];
    const float* Wq_b  = (const float*)d_in[3];
    const float* Wk_w  = (const float*)d_in[4];
    const float* Wk_b  = (const float*)d_in[5];
    const float* Wv_w  = (const float*)d_in[6];
    const float* Wv_b  = (const float*)d_in[7];
    const float* Wo_w  = (const float*)d_in[8];
    const float* Wo_b  = (const float*)d_in[9];
    const float* ln_g  = (const float*)d_in[10];
    const float* ln_b  = (const float*)d_in[11];
    const float* fc_w  = (const float*)d_in[12];
    const float* fc_b  = (const float*)d_in[13];
    const float* out_w = (const float*)d_in[14];
    const float* out_b = (const float*)d_in[15];
    const float* proj  = (const float*)d_in[16];
    const float* gum   = (const float*)d_in[17];
    float* out = (float*)d_out;

    float *q, *k, *v, *qp, *kdd, *kdiag, *krmax, *kmax, *kp, *kvs, *ksum, *z;
    float *h1p, *wpat, *fused, *rden;
    cudaGetSymbolAddress((void**)&q,     g_q);
    cudaGetSymbolAddress((void**)&k,     g_k);
    cudaGetSymbolAddress((void**)&v,     g_v);
    cudaGetSymbolAddress((void**)&qp,    g_qp);
    cudaGetSymbolAddress((void**)&kdd,   g_kdd);
    cudaGetSymbolAddress((void**)&kdiag, g_kdiag);
    cudaGetSymbolAddress((void**)&krmax, g_krmax);
    cudaGetSymbolAddress((void**)&kmax,  g_kmax);
    cudaGetSymbolAddress((void**)&kp,    g_kp);
    cudaGetSymbolAddress((void**)&kvs,   g_kvs);
    cudaGetSymbolAddress((void**)&ksum,  g_ksum);
    cudaGetSymbolAddress((void**)&z,     g_z);
    cudaGetSymbolAddress((void**)&h1p,   g_h1p);
    cudaGetSymbolAddress((void**)&wpat,  g_wpat);
    cudaGetSymbolAddress((void**)&fused, g_fused);
    cudaGetSymbolAddress((void**)&rden,  g_rden);

    // 1) Q/K/V projections
    sgemm_nt<<<dim3(100,4,1), 256>>>(x, Wq_w, Wq_b, q, BL, Dm, Dm, Dm);
    sgemm_nt<<<dim3(100,4,1), 256>>>(x, Wk_w, Wk_b, k, BL, Dm, Dm, Dm);
    sgemm_nt<<<dim3(100,4,1), 256>>>(x, Wv_w, Wv_b, v, BL, Dm, Dm, Dm);

    // 2) Performer feature maps
    phi_kernel<<<BL*Hh, 64>>>(q, proj, qp, nullptr, nullptr, nullptr, 1);
    phi_kernel<<<BL*Hh, 64>>>(k, proj, nullptr, kdd, kdiag, krmax, 0);
    kmax_kernel<<<Bq*Hh, 256>>>(krmax, kmax);
    kp2_kernel<<<(BL*Hh*Mm)/256, 256>>>(kdd, kdiag, kmax, kp);

    // 3) kvs / ksum contraction over tokens
    kvs_kernel<<<Bq*Hh*Kg, 256>>>(kp, v, gum, kvs, ksum);

    // 4) z = mean_k num/den, then LayerNorm
    z_kernel<<<dim3(Bq*Hh, 16), 512>>>(qp, kvs, ksum, z);
    ln_kernel<<<BL*Hh/8, 256>>>(z, ln_g, ln_b);

    // 5) adjacency patch fusion
    sgemm_nt<<<dim3(8,2,NSPLIT), 256>>>(adj, fc_w, nullptr, h1p, 512, 128, 10000, KCHUNK);
    score_kernel<<<Bq*Pp, 256>>>(h1p, fc_b, out_w, out_b, wpat);
    fused_kernel<<<2500, 256>>>(adj, wpat, fused);
    rden_kernel<<<Bq*Pp*Nn/8, 256>>>(fused, rden);

    // 6) relational bias added into z
    biasadd_kernel<<<Bq*Pp, 256>>>(fused, rden, v, z);

    // 7) output projection
    sgemm_nt<<<dim3(100,4,1), 256>>>(z, Wo_w, Wo_b, out, BL, Dm, Dm, Dm);
}

// round 2
// speedup vs baseline: 2.1595x; 2.1595x over previous
#include <cuda_runtime.h>
#include <math.h>

// ---------------- static problem config ----------------
#define Bq    8
#define Pp    8
#define Nn    100
#define Dm    256
#define Hh    8
#define DKk   32
#define Mm    64
#define Kg    16
#define Ll    800            // P*N
#define BL    6400           // B*L
#define NSPLIT 25
#define KCHUNK 400           // 25*400 = 10000

// scale: s * DK^{-0.25} = 2 * 32^{-0.25}
#define PHI_SCALE 0.84089641525f

// ---------------- scratch (device globals; no allocation) ----------------
__device__ __align__(16) float g_q   [BL*Dm];
__device__ __align__(16) float g_k   [BL*Dm];
__device__ __align__(16) float g_v   [BL*Dm];
__device__ __align__(16) float g_qp  [BL*Hh*Mm];
__device__ __align__(16) float g_kdd [BL*Hh*Mm];
__device__              float g_kdiag[BL*Hh];
__device__              float g_krmax[BL*Hh];
__device__              float g_kmax [Bq*Hh];
__device__ __align__(16) float g_kp  [BL*Hh*Mm];
__device__ __align__(16) float g_kvs [Bq*Hh*Kg*Mm*DKk];
__device__ __align__(16) float g_ksum[Bq*Hh*Kg*Mm];
__device__ __align__(16) float g_z   [BL*Dm];
__device__ __align__(16) float g_h1p [NSPLIT*512*128];
__device__              float g_wpat [512];
__device__ __align__(16) float g_fused[Bq*Pp*Nn*Nn];
__device__              float g_rden [Bq*Pp*Nn];

// ---------------- GEMM tile: 128x64, BK=16, 256 thr, 8x4 micro ----------------
// C[row0..+128, col0..+64] = A[Mr,Kd](rows) @ W[Nc,Kd]^T (+bias)
__device__ __forceinline__ void gemm_tile(const float* __restrict__ A,
                                          const float* __restrict__ W,
                                          const float* __restrict__ bias,
                                          float* __restrict__ C,
                                          int Mr, int Nc, int Kd, int k0, int klen)
{
    __shared__ float As[16][132];
    __shared__ float Ws[16][68];
    int tid = threadIdx.x;
    int tx = tid & 15, ty = tid >> 4;
    int row0 = blockIdx.x * 128, col0 = blockIdx.y * 64;

    float acc[8][4];
#pragma unroll
    for (int i = 0; i < 8; i++)
#pragma unroll
        for (int j = 0; j < 4; j++) acc[i][j] = 0.f;

    int ra = tid >> 1, ca = (tid & 1) * 8;   // A: row ra, cols ca..ca+7
    int rw = tid >> 2, cw = (tid & 3) * 4;   // W: row rw, cols cw..cw+3

    for (int kk = k0; kk < k0 + klen; kk += 16) {
        float4 a0 = *(const float4*)&A[(size_t)(row0 + ra) * Kd + kk + ca];
        float4 a1 = *(const float4*)&A[(size_t)(row0 + ra) * Kd + kk + ca + 4];
        As[ca+0][ra] = a0.x; As[ca+1][ra] = a0.y; As[ca+2][ra] = a0.z; As[ca+3][ra] = a0.w;
        As[ca+4][ra] = a1.x; As[ca+5][ra] = a1.y; As[ca+6][ra] = a1.z; As[ca+7][ra] = a1.w;
        float4 w4 = *(const float4*)&W[(size_t)(col0 + rw) * Kd + kk + cw];
        Ws[cw+0][rw] = w4.x; Ws[cw+1][rw] = w4.y; Ws[cw+2][rw] = w4.z; Ws[cw+3][rw] = w4.w;
        __syncthreads();
#pragma unroll
        for (int c = 0; c < 16; c++) {
            float4 av0 = *(const float4*)&As[c][ty*8];
            float4 av1 = *(const float4*)&As[c][ty*8 + 4];
            float4 wv  = *(const float4*)&Ws[c][tx*4];
            float a[8] = {av0.x, av0.y, av0.z, av0.w, av1.x, av1.y, av1.z, av1.w};
            float w[4] = {wv.x, wv.y, wv.z, wv.w};
#pragma unroll
            for (int i = 0; i < 8; i++)
#pragma unroll
                for (int j = 0; j < 4; j++) acc[i][j] += a[i] * w[j];
        }
        __syncthreads();
    }

    float4 bv = make_float4(0.f, 0.f, 0.f, 0.f);
    if (bias) bv = *(const float4*)&bias[col0 + tx*4];
#pragma unroll
    for (int i = 0; i < 8; i++) {
        int rr = row0 + ty*8 + i;
        float4 o;
        o.x = acc[i][0] + bv.x;
        o.y = acc[i][1] + bv.y;
        o.z = acc[i][2] + bv.z;
        o.w = acc[i][3] + bv.w;
        *(float4*)&C[(size_t)rr * Nc + col0 + tx*4] = o;
    }
}

// fused QKV: blockIdx.z selects target
__global__ void qkv_gemm(const float* __restrict__ A,
                         const float* __restrict__ Wq, const float* __restrict__ Wk,
                         const float* __restrict__ Wv,
                         const float* __restrict__ bq, const float* __restrict__ bk,
                         const float* __restrict__ bv,
                         float* __restrict__ q, float* __restrict__ k, float* __restrict__ v)
{
    const float* W    = blockIdx.z == 0 ? Wq : (blockIdx.z == 1 ? Wk : Wv);
    const float* bias = blockIdx.z == 0 ? bq : (blockIdx.z == 1 ? bk : bv);
    float* C          = blockIdx.z == 0 ? q  : (blockIdx.z == 1 ? k  : v);
    gemm_tile(A, W, bias, C, BL, Dm, Dm, 0, Dm);
}

__global__ void gemm_single(const float* __restrict__ A, const float* __restrict__ W,
                            const float* __restrict__ bias, float* __restrict__ C,
                            int Mr, int Nc, int Kd)
{
    gemm_tile(A, W, bias, C, Mr, Nc, Kd, 0, Kd);
}

// split-K partials: blockIdx.z = split
__global__ void gemm_sk(const float* __restrict__ A, const float* __restrict__ W,
                        float* __restrict__ C, int Mr, int Nc, int Kd, int klen)
{
    gemm_tile(A, W, nullptr, C + (size_t)blockIdx.z * (size_t)Mr * Nc,
              Mr, Nc, Kd, blockIdx.z * klen, klen);
}

// ---------------- Performer feature map ----------------
// 256 threads; 16 units per block; proj staged in smem once.
__global__ void phi_kernel(const float* __restrict__ din, const float* __restrict__ proj,
                           float* __restrict__ outphi, float* __restrict__ dd_out,
                           float* __restrict__ diag_out, float* __restrict__ rmax_out,
                           int is_query)
{
    __shared__ float proj_s[64][33];
    __shared__ float data_s[4][32];
    __shared__ float wmax[4][2];
    int tid = threadIdx.x;
    for (int i = tid; i < 2048; i += 256) proj_s[i >> 5][i & 31] = proj[i];
    int sub = tid >> 6;          // 0..3
    int m = tid & 63;
    int u0 = blockIdx.x * 16;
    for (int g = 0; g < 16; g += 4) {
        int u = u0 + g + sub;
        __syncthreads();
        if (m < 32) data_s[sub][m] = din[(size_t)u*32 + m] * PHI_SCALE;
        __syncthreads();
        float dd = 0.f, diag = 0.f;
#pragma unroll
        for (int d = 0; d < 32; d++) {
            float x = data_s[sub][d];
            dd   += x * proj_s[m][d];
            diag += x * x;
        }
        diag *= 0.5f;
        float mx = dd;
#pragma unroll
        for (int o = 16; o > 0; o >>= 1) mx = fmaxf(mx, __shfl_xor_sync(0xffffffffu, mx, o));
        if ((tid & 31) == 0) wmax[sub][m >> 5] = mx;
        __syncthreads();
        float stab = fmaxf(wmax[sub][0], wmax[sub][1]);
        if (is_query) {
            outphi[(size_t)u*64 + m] = 0.125f * (expf(dd - diag - stab) + 1e-6f);
        } else {
            dd_out[(size_t)u*64 + m] = dd;
            if (m == 0) { diag_out[u] = diag; rmax_out[u] = stab; }
        }
    }
}

// key stabilizer: max over tokens per (b,h)
__global__ void kmax_kernel(const float* __restrict__ rmax, float* __restrict__ kmax)
{
    int bh = blockIdx.x; int b = bh >> 3, h = bh & 7;
    int t = threadIdx.x;
    __shared__ float red[256];
    float mx = -1e30f;
    for (int l = t; l < Ll; l += 256) mx = fmaxf(mx, rmax[(b*Ll + l)*Hh + h]);
    red[t] = mx; __syncthreads();
    for (int s = 128; s > 0; s >>= 1) { if (t < s) red[t] = fmaxf(red[t], red[t+s]); __syncthreads(); }
    if (t == 0) kmax[bh] = red[0];
}

__global__ void kp2_kernel(const float* __restrict__ dd, const float* __restrict__ diag,
                           const float* __restrict__ kmax, float* __restrict__ kp)
{
    int i = blockIdx.x * 256 + threadIdx.x;   // < BL*H*M
    int u = i >> 6;
    int b = u / (Ll * Hh);
    int h = u & 7;
    kp[i] = 0.125f * (expf(dd[i] - diag[u] - kmax[b*Hh + h]) + 1e-6f);
}

// ---------------- kvs + ksum: contract over L (chunk 16) ----------------
__global__ void kvs_kernel(const float* __restrict__ kp, const float* __restrict__ v,
                           const float* __restrict__ gum,
                           float* __restrict__ kvs, float* __restrict__ ksum)
{
    int bhk = blockIdx.x;
    int k = bhk & 15, h = (bhk >> 4) & 7, b = bhk >> 7;
    int t = threadIdx.x;
    int d = t & 31, mr = t >> 5;
    __shared__ float kp_s[16][64];
    __shared__ float v_s[16][32];
    __shared__ float e_s[16];
    float acc[8];
#pragma unroll
    for (int j = 0; j < 8; j++) acc[j] = 0.f;
    float s = 0.f;

    for (int l0 = 0; l0 < Ll; l0 += 16) {
        __syncthreads();
        {   // kp: 1024 floats as 256 float4
            int c = t >> 4, m4 = (t & 15) * 4;
            *(float4*)&kp_s[c][m4] =
                *(const float4*)&kp[((size_t)((b*Ll + l0 + c)*Hh + h) << 6) + m4];
        }
        {   int c = t >> 5;
            v_s[c][d]     = v[(size_t)(b*Ll + l0 + c)*Dm     + h*32 + d];
            v_s[c + 8][d] = v[(size_t)(b*Ll + l0 + c + 8)*Dm + h*32 + d];
        }
        if (t < 16) e_s[t] = expf(gum[(((b*Ll + l0 + t)*Hh + h) << 4) + k]);
        __syncthreads();
#pragma unroll
        for (int c = 0; c < 16; c++) {
            float ve = v_s[c][d] * e_s[c];
#pragma unroll
            for (int j = 0; j < 8; j++) acc[j] += kp_s[c][mr + 8*j] * ve;
        }
        if (t < 64) {
#pragma unroll
            for (int c = 0; c < 16; c++) s += kp_s[c][t] * e_s[c];
        }
    }
    size_t base = (size_t)bhk * 64 * 32;
#pragma unroll
    for (int j = 0; j < 8; j++) kvs[base + (size_t)(mr + 8*j)*32 + d] = acc[j];
    if (t < 64) ksum[(size_t)bhk*64 + t] = s;
}

// ---------------- z = mean_k (qp @ kvs[k]) / (qp @ ksum[k]) ----------------
// grid (64, 20): chunks of 40 tokens, 4 tokens per barrier round.
__global__ void z_kernel(const float* __restrict__ qp, const float* __restrict__ kvs,
                         const float* __restrict__ ksum, float* __restrict__ z)
{
    int bh = blockIdx.x; int b = bh >> 3, h = bh & 7;
    int l0 = blockIdx.y * 40;
    int t = threadIdx.x;
    int d = t & 31, k = t >> 5;
    __shared__ float qp_s[4][64];
    __shared__ float ks_s[1024];
    __shared__ float sred[4][512];

    float kv[64];
#pragma unroll
    for (int m = 0; m < 64; m++)
        kv[m] = kvs[((size_t)(bh*16 + k)*64 + m)*32 + d];
    for (int i = t; i < 1024; i += 512) ks_s[i] = ksum[(size_t)bh*1024 + i];

    for (int li = 0; li < 40; li += 4) {
        __syncthreads();
        if (t < 256) {
            int ti = t >> 6, m = t & 63;
            qp_s[ti][m] = qp[(size_t)((b*Ll + l0 + li + ti)*Hh + h)*64 + m];
        }
        __syncthreads();
#pragma unroll
        for (int ti = 0; ti < 4; ti++) {
            float den = qp_s[ti][d]      * ks_s[k*64 + d]
                      + qp_s[ti][d + 32] * ks_s[k*64 + d + 32];
#pragma unroll
            for (int o = 16; o > 0; o >>= 1) den += __shfl_xor_sync(0xffffffffu, den, o);
            den += 1e-8f;
            float num = 0.f;
#pragma unroll
            for (int m = 0; m < 64; m++) num += qp_s[ti][m] * kv[m];
            sred[ti][t] = num / (den * 16.0f);
        }
        __syncthreads();
        if (t < 128) {
            int ti = t >> 5, dd2 = t & 31;
            float ss = 0.f;
#pragma unroll
            for (int kk = 0; kk < 16; kk++) ss += sred[ti][kk*32 + dd2];
            z[(size_t)(b*Ll + l0 + li + ti)*Dm + h*32 + dd2] = ss;
        }
    }
}

// ---------------- LayerNorm over DK per (b,l,h), in-place ----------------
__global__ void ln_kernel(float* __restrict__ z, const float* __restrict__ g,
                          const float* __restrict__ bb)
{
    int w = threadIdx.x >> 5, lane = threadIdx.x & 31;
    int u = blockIdx.x * 8 + w;                 // < BL*H
    float x = z[(size_t)u*32 + lane];
    float mu = x;
#pragma unroll
    for (int o = 16; o > 0; o >>= 1) mu += __shfl_xor_sync(0xffffffffu, mu, o);
    mu *= (1.0f / 32.0f);
    float df = x - mu;
    float v2 = df * df;
#pragma unroll
    for (int o = 16; o > 0; o >>= 1) v2 += __shfl_xor_sync(0xffffffffu, v2, o);
    float var = v2 * (1.0f / 32.0f);
    z[(size_t)u*32 + lane] = df * rsqrtf(var + 1e-5f) * g[lane] + bb[lane];
}

// ---------------- patch score + softmax over patch dim ----------------
__global__ void score_kernel(const float* __restrict__ h1p, const float* __restrict__ fc_b,
                             const float* __restrict__ out_w, const float* __restrict__ out_b,
                             float* __restrict__ wout)
{
    int bp = blockIdx.x;                        // < 64
    int t = threadIdx.x >> 5, lane = threadIdx.x & 31;
    __shared__ float sc[8];
    float p = 0.f;
    for (int j = lane; j < 128; j += 32) {
        float hv = fc_b[j];
        for (int s = 0; s < NSPLIT; s++) hv += h1p[(size_t)s*65536 + (bp*8 + t)*128 + j];
        hv = fmaxf(hv, 0.f);
        p += hv * out_w[j];
    }
#pragma unroll
    for (int o = 16; o > 0; o >>= 1) p += __shfl_xor_sync(0xffffffffu, p, o);
    if (lane == 0) sc[t] = p + out_b[0];
    __syncthreads();
    if (threadIdx.x == 0) {
        float mx = sc[0];
#pragma unroll
        for (int i = 1; i < 8; i++) mx = fmaxf(mx, sc[i]);
        float e[8], sum = 0.f;
#pragma unroll
        for (int i = 0; i < 8; i++) { e[i] = expf(sc[i] - mx); sum += e[i]; }
#pragma unroll
        for (int i = 0; i < 8; i++) wout[bp*8 + i] = e[i] / sum;
    }
}

// fused[b,p,i,j] = sum_t adj[b, p*8+t, i, j] * w[bp,t]
__global__ void fused_kernel(const float* __restrict__ adj, const float* __restrict__ wpat,
                             float* __restrict__ fused)
{
    int idx = blockIdx.x * 256 + threadIdx.x;   // < 640000
    int bp = idx / 10000;
    int rem = idx - bp * 10000;
    float s = 0.f;
#pragma unroll
    for (int t = 0; t < 8; t++) s += adj[(size_t)(bp*8 + t)*10000 + rem] * wpat[bp*8 + t];
    fused[idx] = s;
}

// row L1 norm denominators
__global__ void rden_kernel(const float* __restrict__ fused, float* __restrict__ rden)
{
    int w = threadIdx.x >> 5, lane = threadIdx.x & 31;
    int row = blockIdx.x * 8 + w;               // < 6400
    float s = 0.f;
    for (int j = lane; j < 100; j += 32) s += fabsf(fused[(size_t)row*100 + j]);
#pragma unroll
    for (int o = 16; o > 0; o >>= 1) s += __shfl_xor_sync(0xffffffffu, s, o);
    if (lane == 0) rden[row] = fmaxf(s, 1e-12f);
}

// relational bias: z += (fused/rden) @ V  per (b,p) block-diagonal
__global__ void biasadd_kernel(const float* __restrict__ fused, const float* __restrict__ rden,
                               const float* __restrict__ v, float* __restrict__ z)
{
    __shared__ float A_s[100][101];
    int blk = blockIdx.x;                       // b*8+p
    int t = threadIdx.x;                        // 256 -> column d
    for (int idx = t; idx < 10000; idx += 256) {
        int i = idx / 100, j = idx - i * 100;
        A_s[i][j] = fused[(size_t)blk*10000 + idx] / rden[blk*100 + i];
    }
    __syncthreads();
    int base = blk * 100;
    for (int i0 = 0; i0 < 100; i0 += 20) {
        float acc[20];
#pragma unroll
        for (int ii = 0; ii < 20; ii++) acc[ii] = 0.f;
        for (int j = 0; j < 100; j++) {
            float vj = v[(size_t)(base + j)*256 + t];
#pragma unroll
            for (int ii = 0; ii < 20; ii++) acc[ii] += A_s[i0 + ii][j] * vj;
        }
#pragma unroll
        for (int ii = 0; ii < 20; ii++)
            z[(size_t)(base + i0 + ii)*256 + t] += acc[ii];
    }
}

// ---------------- launcher ----------------
extern "C" void kernel_launch(void* const* d_in, const int* in_sizes, int n_in,
                              void* d_out, int out_size)
{
    const float* x     = (const float*)d_in[0];
    const float* adj   = (const float*)d_in[1];
    const float* Wq_w  = (const float*)d_in[2];
    const float* Wq_b  = (const float*)d_in[3];
    const float* Wk_w  = (const float*)d_in[4];
    const float* Wk_b  = (const float*)d_in[5];
    const float* Wv_w  = (const float*)d_in[6];
    const float* Wv_b  = (const float*)d_in[7];
    const float* Wo_w  = (const float*)d_in[8];
    const float* Wo_b  = (const float*)d_in[9];
    const float* ln_g  = (const float*)d_in[10];
    const float* ln_b  = (const float*)d_in[11];
    const float* fc_w  = (const float*)d_in[12];
    const float* fc_b  = (const float*)d_in[13];
    const float* out_w = (const float*)d_in[14];
    const float* out_b = (const float*)d_in[15];
    const float* proj  = (const float*)d_in[16];
    const float* gum   = (const float*)d_in[17];
    float* out = (float*)d_out;

    float *q, *k, *v, *qp, *kdd, *kdiag, *krmax, *kmax, *kp, *kvs, *ksum, *z;
    float *h1p, *wpat, *fused, *rden;
    cudaGetSymbolAddress((void**)&q,     g_q);
    cudaGetSymbolAddress((void**)&k,     g_k);
    cudaGetSymbolAddress((void**)&v,     g_v);
    cudaGetSymbolAddress((void**)&qp,    g_qp);
    cudaGetSymbolAddress((void**)&kdd,   g_kdd);
    cudaGetSymbolAddress((void**)&kdiag, g_kdiag);
    cudaGetSymbolAddress((void**)&krmax, g_krmax);
    cudaGetSymbolAddress((void**)&kmax,  g_kmax);
    cudaGetSymbolAddress((void**)&kp,    g_kp);
    cudaGetSymbolAddress((void**)&kvs,   g_kvs);
    cudaGetSymbolAddress((void**)&ksum,  g_ksum);
    cudaGetSymbolAddress((void**)&z,     g_z);
    cudaGetSymbolAddress((void**)&h1p,   g_h1p);
    cudaGetSymbolAddress((void**)&wpat,  g_wpat);
    cudaGetSymbolAddress((void**)&fused, g_fused);
    cudaGetSymbolAddress((void**)&rden,  g_rden);

    // 1) fused Q/K/V projections (600 blocks)
    qkv_gemm<<<dim3(BL/128, Dm/64, 3), 256>>>(x, Wq_w, Wk_w, Wv_w,
                                              Wq_b, Wk_b, Wv_b, q, k, v);

    // 2) Performer feature maps
    phi_kernel<<<BL*Hh/16, 256>>>(q, proj, qp, nullptr, nullptr, nullptr, 1);
    phi_kernel<<<BL*Hh/16, 256>>>(k, proj, nullptr, kdd, kdiag, krmax, 0);
    kmax_kernel<<<Bq*Hh, 256>>>(krmax, kmax);
    kp2_kernel<<<(BL*Hh*Mm)/256, 256>>>(kdd, kdiag, kmax, kp);

    // 3) kvs / ksum contraction over tokens
    kvs_kernel<<<Bq*Hh*Kg, 256>>>(kp, v, gum, kvs, ksum);

    // 4) z = mean_k num/den, then LayerNorm
    z_kernel<<<dim3(Bq*Hh, 20), 512>>>(qp, kvs, ksum, z);
    ln_kernel<<<BL*Hh/8, 256>>>(z, ln_g, ln_b);

    // 5) adjacency patch fusion
    gemm_sk<<<dim3(512/128, 128/64, NSPLIT), 256>>>(adj, fc_w, h1p, 512, 128, 10000, KCHUNK);
    score_kernel<<<Bq*Pp, 256>>>(h1p, fc_b, out_w, out_b, wpat);
    fused_kernel<<<2500, 256>>>(adj, wpat, fused);
    rden_kernel<<<Bq*Pp*Nn/8, 256>>>(fused, rden);

    // 6) relational bias added into z
    biasadd_kernel<<<Bq*Pp, 256>>>(fused, rden, v, z);

    // 7) output projection
    gemm_single<<<dim3(BL/128, Dm/64, 1), 256>>>(z, Wo_w, Wo_b, out, BL, Dm, Dm);
}

// round 3
// speedup vs baseline: 2.5663x; 1.1884x over previous
#include <cuda_runtime.h>
#include <math.h>

// ---------------- static problem config ----------------
#define Bq    8
#define Pp    8
#define Nn    100
#define Dm    256
#define Hh    8
#define DKk   32
#define Mm    64
#define Kg    16
#define Ll    800            // P*N
#define BL    6400           // B*L
#define NSPLIT 25
#define KCHUNK 400           // 25*400 = 10000

#define PHI_SCALE 0.84089641525f   // 2 * 32^-0.25

// ---------------- scratch (device globals; no allocation) ----------------
__device__ __align__(16) float g_q   [BL*Dm];
__device__ __align__(16) float g_k   [BL*Dm];
__device__ __align__(16) float g_v   [BL*Dm];
__device__ __align__(16) float g_qp  [BL*Hh*Mm];
__device__ __align__(16) float g_kdd [BL*Hh*Mm];
__device__              float g_kdiag[BL*Hh];
__device__              float g_krmax[BL*Hh];
__device__              float g_kmax [Bq*Hh];
__device__ __align__(16) float g_kp  [BL*Hh*Mm];
__device__ __align__(16) float g_eg  [BL*Hh*Kg];
__device__ __align__(16) float g_kvs [Bq*Hh*Kg*Mm*DKk];
__device__ __align__(16) float g_ksum[Bq*Hh*Kg*Mm];
__device__ __align__(16) float g_winv[BL*Hh*Kg];
__device__ __align__(16) float g_z   [BL*Dm];
__device__ __align__(16) float g_h1p [NSPLIT*512*128];
__device__              float g_wpat [512];
__device__ __align__(16) float g_fused[Bq*Pp*Nn*Nn];
__device__              float g_rden [Bq*Pp*Nn];

// ======== GEMM: 128x128 tile, BK=16, 256 thr, 8x8 micro, double buffered ========
// C[row0..+128, col0..+128] = A[rows,Kd] @ W[Nc,Kd]^T (+bias)
__device__ __forceinline__ void gemm128(const float* __restrict__ A,
                                        const float* __restrict__ W,
                                        const float* __restrict__ bias,
                                        float* __restrict__ C,
                                        int Nc, int Kd, int k0, int klen)
{
    __shared__ float As[2][16][132];
    __shared__ float Ws[2][16][132];
    int tid = threadIdx.x;
    int tx = tid & 15, ty = tid >> 4;
    int row0 = blockIdx.x * 128, col0 = blockIdx.y * 128;
    int lr = tid >> 1, lc = (tid & 1) * 8;

    const float* Ap = A + (size_t)(row0 + lr) * Kd + k0 + lc;
    const float* Wp = W + (size_t)(col0 + lr) * Kd + k0 + lc;

    float acc[8][8];
#pragma unroll
    for (int i = 0; i < 8; i++)
#pragma unroll
        for (int j = 0; j < 8; j++) acc[i][j] = 0.f;

    float4 pa0 = *(const float4*)(Ap);
    float4 pa1 = *(const float4*)(Ap + 4);
    float4 pw0 = *(const float4*)(Wp);
    float4 pw1 = *(const float4*)(Wp + 4);

    int nk = klen >> 4;
    int buf = 0;
    for (int it = 0; it < nk; it++) {
        As[buf][lc+0][lr] = pa0.x; As[buf][lc+1][lr] = pa0.y;
        As[buf][lc+2][lr] = pa0.z; As[buf][lc+3][lr] = pa0.w;
        As[buf][lc+4][lr] = pa1.x; As[buf][lc+5][lr] = pa1.y;
        As[buf][lc+6][lr] = pa1.z; As[buf][lc+7][lr] = pa1.w;
        Ws[buf][lc+0][lr] = pw0.x; Ws[buf][lc+1][lr] = pw0.y;
        Ws[buf][lc+2][lr] = pw0.z; Ws[buf][lc+3][lr] = pw0.w;
        Ws[buf][lc+4][lr] = pw1.x; Ws[buf][lc+5][lr] = pw1.y;
        Ws[buf][lc+6][lr] = pw1.z; Ws[buf][lc+7][lr] = pw1.w;
        __syncthreads();
        if (it + 1 < nk) {
            int off = (it + 1) * 16;
            pa0 = *(const float4*)(Ap + off);
            pa1 = *(const float4*)(Ap + off + 4);
            pw0 = *(const float4*)(Wp + off);
            pw1 = *(const float4*)(Wp + off + 4);
        }
#pragma unroll
        for (int c = 0; c < 16; c++) {
            float4 a0 = *(const float4*)&As[buf][c][ty*4];
            float4 a1 = *(const float4*)&As[buf][c][64 + ty*4];
            float4 w0 = *(const float4*)&Ws[buf][c][tx*4];
            float4 w1 = *(const float4*)&Ws[buf][c][64 + tx*4];
            float a[8] = {a0.x,a0.y,a0.z,a0.w, a1.x,a1.y,a1.z,a1.w};
            float w[8] = {w0.x,w0.y,w0.z,w0.w, w1.x,w1.y,w1.z,w1.w};
#pragma unroll
            for (int i = 0; i < 8; i++)
#pragma unroll
                for (int j = 0; j < 8; j++) acc[i][j] += a[i] * w[j];
        }
        buf ^= 1;
    }

    float4 b0 = make_float4(0,0,0,0), b1 = make_float4(0,0,0,0);
    if (bias) {
        b0 = *(const float4*)&bias[col0 + tx*4];
        b1 = *(const float4*)&bias[col0 + 64 + tx*4];
    }
#pragma unroll
    for (int i = 0; i < 8; i++) {
        int rr = row0 + ((i < 4) ? (ty*4 + i) : (64 + ty*4 + i - 4));
        float4 o0, o1;
        o0.x = acc[i][0]+b0.x; o0.y = acc[i][1]+b0.y; o0.z = acc[i][2]+b0.z; o0.w = acc[i][3]+b0.w;
        o1.x = acc[i][4]+b1.x; o1.y = acc[i][5]+b1.y; o1.z = acc[i][6]+b1.z; o1.w = acc[i][7]+b1.w;
        *(float4*)&C[(size_t)rr * Nc + col0 + tx*4]      = o0;
        *(float4*)&C[(size_t)rr * Nc + col0 + 64 + tx*4] = o1;
    }
}

__global__ void qkv_gemm(const float* __restrict__ A,
                         const float* __restrict__ Wq, const float* __restrict__ Wk,
                         const float* __restrict__ Wv,
                         const float* __restrict__ bq, const float* __restrict__ bk,
                         const float* __restrict__ bv,
                         float* __restrict__ q, float* __restrict__ k, float* __restrict__ v)
{
    const float* W    = blockIdx.z == 0 ? Wq : (blockIdx.z == 1 ? Wk : Wv);
    const float* bias = blockIdx.z == 0 ? bq : (blockIdx.z == 1 ? bk : bv);
    float* C          = blockIdx.z == 0 ? q  : (blockIdx.z == 1 ? k  : v);
    gemm128(A, W, bias, C, Dm, Dm, 0, Dm);
}

__global__ void gemm_single(const float* __restrict__ A, const float* __restrict__ W,
                            const float* __restrict__ bias, float* __restrict__ C,
                            int Nc, int Kd)
{
    gemm128(A, W, bias, C, Nc, Kd, 0, Kd);
}

__global__ void gemm_sk(const float* __restrict__ A, const float* __restrict__ W,
                        float* __restrict__ C, int Mr, int Nc, int Kd, int klen)
{
    gemm128(A, W, nullptr, C + (size_t)blockIdx.z * (size_t)Mr * Nc,
            Nc, Kd, blockIdx.z * klen, klen);
}

// ---------------- Performer feature map ----------------
__global__ void phi_kernel(const float* __restrict__ din, const float* __restrict__ proj,
                           float* __restrict__ outphi, float* __restrict__ dd_out,
                           float* __restrict__ diag_out, float* __restrict__ rmax_out,
                           int is_query)
{
    __shared__ float proj_s[64][33];
    __shared__ float data_s[4][32];
    __shared__ float wmax[4][2];
    int tid = threadIdx.x;
    for (int i = tid; i < 2048; i += 256) proj_s[i >> 5][i & 31] = proj[i];
    int sub = tid >> 6;
    int m = tid & 63;
    int u0 = blockIdx.x * 16;
    for (int g = 0; g < 16; g += 4) {
        int u = u0 + g + sub;
        __syncthreads();
        if (m < 32) data_s[sub][m] = din[(size_t)u*32 + m] * PHI_SCALE;
        __syncthreads();
        float dd = 0.f, diag = 0.f;
#pragma unroll
        for (int d = 0; d < 32; d++) {
            float x = data_s[sub][d];
            dd   += x * proj_s[m][d];
            diag += x * x;
        }
        diag *= 0.5f;
        float mx = dd;
#pragma unroll
        for (int o = 16; o > 0; o >>= 1) mx = fmaxf(mx, __shfl_xor_sync(0xffffffffu, mx, o));
        if ((tid & 31) == 0) wmax[sub][m >> 5] = mx;
        __syncthreads();
        float stab = fmaxf(wmax[sub][0], wmax[sub][1]);
        if (is_query) {
            outphi[(size_t)u*64 + m] = 0.125f * (expf(dd - diag - stab) + 1e-6f);
        } else {
            dd_out[(size_t)u*64 + m] = dd;
            if (m == 0) { diag_out[u] = diag; rmax_out[u] = stab; }
        }
    }
}

__global__ void kmax_kernel(const float* __restrict__ rmax, float* __restrict__ kmax)
{
    int bh = blockIdx.x; int b = bh >> 3, h = bh & 7;
    int t = threadIdx.x;
    __shared__ float red[256];
    float mx = -1e30f;
    for (int l = t; l < Ll; l += 256) mx = fmaxf(mx, rmax[(b*Ll + l)*Hh + h]);
    red[t] = mx; __syncthreads();
    for (int s = 128; s > 0; s >>= 1) { if (t < s) red[t] = fmaxf(red[t], red[t+s]); __syncthreads(); }
    if (t == 0) kmax[bh] = red[0];
}

__global__ void kp2_kernel(const float* __restrict__ dd, const float* __restrict__ diag,
                           const float* __restrict__ kmax, float* __restrict__ kp)
{
    int i = blockIdx.x * 256 + threadIdx.x;
    int u = i >> 6;
    int b = u / (Ll * Hh);
    int h = u & 7;
    kp[i] = 0.125f * (expf(dd[i] - diag[u] - kmax[b*Hh + h]) + 1e-6f);
}

// exp of gumbels, elementwise
__global__ void eg_kernel(const float* __restrict__ gum, float* __restrict__ eg)
{
    int i = blockIdx.x * 256 + threadIdx.x;
    if (i < BL*Hh*Kg) eg[i] = expf(gum[i]);
}

// ---------------- ksum[bh][k][m] = sum_l kp[l,m] * eg[l,k] ----------------
__global__ void ksum_kernel(const float* __restrict__ kp, const float* __restrict__ eg,
                            float* __restrict__ ksum)
{
    __shared__ float kp_s[16][64];
    __shared__ float eg_s[16][16];
    int bh = blockIdx.x; int b = bh >> 3, h = bh & 7;
    int t = threadIdx.x;
    int lc = t >> 4, lf = t & 15;
    float4 acc = make_float4(0,0,0,0);
    for (int l0 = 0; l0 < Ll; l0 += 16) {
        __syncthreads();
        *(float4*)&kp_s[lc][lf*4] =
            *(const float4*)&kp[((size_t)((b*Ll + l0 + lc)*Hh + h) << 6) + lf*4];
        eg_s[lc][lf] = eg[(((b*Ll + l0 + lc)*Hh + h) << 4) + lf];
        __syncthreads();
#pragma unroll
        for (int c = 0; c < 16; c++) {
            float e = eg_s[c][lc];      // k = lc
            float4 kp4 = *(const float4*)&kp_s[c][lf*4];
            acc.x += kp4.x * e; acc.y += kp4.y * e;
            acc.z += kp4.z * e; acc.w += kp4.w * e;
        }
    }
    // thread (k=lc, m4=lf)
    *(float4*)&ksum[((size_t)(bh*16 + lc) << 6) + lf*4] = acc;
}

// ---------------- winv[l,k] = 1/((qp . ksum + 1e-8)*16) per bh ----------------
__global__ void winv_kernel(const float* __restrict__ qp, const float* __restrict__ ksum,
                            float* __restrict__ winv)
{
    __shared__ float ks_s[16][64];
    __shared__ float qp_s[16][64];
    int bh = blockIdx.x; int b = bh >> 3, h = bh & 7;
    int t = threadIdx.x;
    int lc = t >> 4, lf = t & 15;
    *(float4*)&ks_s[lc][lf*4] = *(const float4*)&ksum[((size_t)(bh*16 + lc) << 6) + lf*4];
    for (int l0 = 0; l0 < Ll; l0 += 16) {
        __syncthreads();
        *(float4*)&qp_s[lc][lf*4] =
            *(const float4*)&qp[((size_t)((b*Ll + l0 + lc)*Hh + h) << 6) + lf*4];
        __syncthreads();
        // thread (li=lc, k=lf)
        float den = 0.f;
#pragma unroll
        for (int m4 = 0; m4 < 16; m4++) {
            float4 q4 = *(const float4*)&qp_s[lc][m4*4];
            float4 k4 = *(const float4*)&ks_s[lf][m4*4];
            den += q4.x*k4.x + q4.y*k4.y + q4.z*k4.z + q4.w*k4.w;
        }
        winv[(((b*Ll + l0 + lc)*Hh + h) << 4) + lf] = 1.0f / ((den + 1e-8f) * 16.0f);
    }
}

// ---------------- kvs[bhk][m][d] = sum_l kp[l,m]*eg[l,k]*v[l,d] ----------------
// 128 threads: thread (mi=t>>3 -> m0=mi*4, di=t&7 -> d0=di*4), 4x4 register tile.
__global__ void kvs_kernel(const float* __restrict__ kp, const float* __restrict__ v,
                           const float* __restrict__ eg, float* __restrict__ kvs)
{
    __shared__ float kp_s[16][64];
    __shared__ float v_s[16][32];
    int bhk = blockIdx.x;
    int k = bhk & 15, h = (bhk >> 4) & 7, b = bhk >> 7;
    int t = threadIdx.x;
    int mi = t >> 3, di = t & 7;
    int m0 = mi * 4, d0 = di * 4;
    int lc = t >> 3, lf = t & 7;

    float acc[4][4];
#pragma unroll
    for (int i = 0; i < 4; i++)
#pragma unroll
        for (int j = 0; j < 4; j++) acc[i][j] = 0.f;

    for (int l0 = 0; l0 < Ll; l0 += 16) {
        __syncthreads();
        size_t ubase = (size_t)((b*Ll + l0 + lc)*Hh + h);
        *(float4*)&kp_s[lc][lf*4]      = *(const float4*)&kp[(ubase << 6) + lf*4];
        *(float4*)&kp_s[lc][lf*4 + 32] = *(const float4*)&kp[(ubase << 6) + lf*4 + 32];
        float e = eg[(ubase << 4) + k];
        float4 v4 = *(const float4*)&v[(size_t)(b*Ll + l0 + lc)*Dm + h*32 + lf*4];
        v4.x *= e; v4.y *= e; v4.z *= e; v4.w *= e;
        *(float4*)&v_s[lc][lf*4] = v4;
        __syncthreads();
#pragma unroll
        for (int c = 0; c < 16; c++) {
            float4 kp4 = *(const float4*)&kp_s[c][m0];
            float4 vv4 = *(const float4*)&v_s[c][d0];
            float a[4] = {kp4.x, kp4.y, kp4.z, kp4.w};
            float w[4] = {vv4.x, vv4.y, vv4.z, vv4.w};
#pragma unroll
            for (int i = 0; i < 4; i++)
#pragma unroll
                for (int j = 0; j < 4; j++) acc[i][j] += a[i] * w[j];
        }
    }
    size_t base = (size_t)bhk * 64 * 32;
#pragma unroll
    for (int i = 0; i < 4; i++) {
        float4 o = make_float4(acc[i][0], acc[i][1], acc[i][2], acc[i][3]);
        *(float4*)&kvs[base + (size_t)(m0 + i)*32 + d0] = o;
    }
}

// ---------------- z + LayerNorm fused ----------------
// grid (64, 20): 40 tokens/block, 512 thr = (k = t>>5, d = t&31).
__global__ void z_kernel(const float* __restrict__ qp, const float* __restrict__ kvs,
                         const float* __restrict__ winv, float* __restrict__ z,
                         const float* __restrict__ ln_g, const float* __restrict__ ln_b)
{
    int bh = blockIdx.x; int b = bh >> 3, h = bh & 7;
    int l0 = blockIdx.y * 40;
    int t = threadIdx.x;
    int d = t & 31, k = t >> 5;
    __shared__ float qp_s[4][64];
    __shared__ float wi_s[4][16];
    __shared__ float sred[4][512];

    float kv[64];
#pragma unroll
    for (int m = 0; m < 64; m++)
        kv[m] = kvs[((size_t)(bh*16 + k)*64 + m)*32 + d];

    float gl = 0.f, bl = 0.f;
    if (t < 128) { gl = ln_g[t & 31]; bl = ln_b[t & 31]; }

    for (int li = 0; li < 40; li += 4) {
        __syncthreads();
        if (t < 64) {
            int ti = t >> 4, f = t & 15;
            *(float4*)&qp_s[ti][f*4] =
                *(const float4*)&qp[((size_t)((b*Ll + l0 + li + ti)*Hh + h) << 6) + f*4];
        } else if (t < 128) {
            int tt = t - 64, ti = tt >> 4, kk = tt & 15;
            wi_s[ti][kk] = winv[(((b*Ll + l0 + li + ti)*Hh + h) << 4) + kk];
        }
        __syncthreads();
#pragma unroll
        for (int ti = 0; ti < 4; ti++) {
            float num = 0.f;
#pragma unroll
            for (int m4 = 0; m4 < 16; m4++) {
                float4 q4 = *(const float4*)&qp_s[ti][m4*4];
                num += q4.x * kv[m4*4]   + q4.y * kv[m4*4+1]
                     + q4.z * kv[m4*4+2] + q4.w * kv[m4*4+3];
            }
            sred[ti][t] = num * wi_s[ti][k];
        }
        __syncthreads();
        if (t < 128) {
            int ti = t >> 5, d2 = t & 31;
            float ss = 0.f;
#pragma unroll
            for (int kk = 0; kk < 16; kk++) ss += sred[ti][kk*32 + d2];
            // fused LayerNorm over the 32 lanes of this warp (one token each)
            float mu = ss;
#pragma unroll
            for (int o = 16; o > 0; o >>= 1) mu += __shfl_xor_sync(0xffffffffu, mu, o);
            mu *= (1.0f / 32.0f);
            float df = ss - mu;
            float v2 = df * df;
#pragma unroll
            for (int o = 16; o > 0; o >>= 1) v2 += __shfl_xor_sync(0xffffffffu, v2, o);
            float var = v2 * (1.0f / 32.0f);
            z[(size_t)(b*Ll + l0 + li + ti)*Dm + h*32 + d2] =
                df * rsqrtf(var + 1e-5f) * gl + bl;
        }
    }
}

// ---------------- patch score + softmax over patch dim ----------------
__global__ void score_kernel(const float* __restrict__ h1p, const float* __restrict__ fc_b,
                             const float* __restrict__ out_w, const float* __restrict__ out_b,
                             float* __restrict__ wout)
{
    int bp = blockIdx.x;
    int t = threadIdx.x >> 5, lane = threadIdx.x & 31;
    __shared__ float sc[8];
    float p = 0.f;
    for (int j = lane; j < 128; j += 32) {
        float hv = fc_b[j];
        for (int s = 0; s < NSPLIT; s++) hv += h1p[(size_t)s*65536 + (bp*8 + t)*128 + j];
        hv = fmaxf(hv, 0.f);
        p += hv * out_w[j];
    }
#pragma unroll
    for (int o = 16; o > 0; o >>= 1) p += __shfl_xor_sync(0xffffffffu, p, o);
    if (lane == 0) sc[t] = p + out_b[0];
    __syncthreads();
    if (threadIdx.x == 0) {
        float mx = sc[0];
#pragma unroll
        for (int i = 1; i < 8; i++) mx = fmaxf(mx, sc[i]);
        float e[8], sum = 0.f;
#pragma unroll
        for (int i = 0; i < 8; i++) { e[i] = expf(sc[i] - mx); sum += e[i]; }
#pragma unroll
        for (int i = 0; i < 8; i++) wout[bp*8 + i] = e[i] / sum;
    }
}

// fused[bp, :] = sum_t adj[bp*8+t, :] * w[bp,t]   (float4)
__global__ void fused_kernel(const float* __restrict__ adj, const float* __restrict__ wpat,
                             float* __restrict__ fused)
{
    int i4 = blockIdx.x * 256 + threadIdx.x;    // < 160000
    if (i4 >= 160000) return;
    int bp = i4 / 2500;
    int r4 = i4 - bp * 2500;
    float4 s = make_float4(0,0,0,0);
#pragma unroll
    for (int t = 0; t < 8; t++) {
        float w = wpat[bp*8 + t];
        float4 a = *(const float4*)&adj[(size_t)(bp*8 + t)*10000 + r4*4];
        s.x += a.x*w; s.y += a.y*w; s.z += a.z*w; s.w += a.w*w;
    }
    *(float4*)&fused[(size_t)bp*10000 + r4*4] = s;
}

__global__ void rden_kernel(const float* __restrict__ fused, float* __restrict__ rden)
{
    int w = threadIdx.x >> 5, lane = threadIdx.x & 31;
    int row = blockIdx.x * 8 + w;
    float s = 0.f;
    for (int j = lane; j < 100; j += 32) s += fabsf(fused[(size_t)row*100 + j]);
#pragma unroll
    for (int o = 16; o > 0; o >>= 1) s += __shfl_xor_sync(0xffffffffu, s, o);
    if (lane == 0) rden[row] = fmaxf(s, 1e-12f);
}

// relational bias: z += (fused/rden) @ V ; grid (64, 5): 20 rows per block
__global__ void biasadd_kernel(const float* __restrict__ fused, const float* __restrict__ rden,
                               const float* __restrict__ v, float* __restrict__ z)
{
    __shared__ float A_s[20][101];
    int blk = blockIdx.x;
    int i0 = blockIdx.y * 20;
    int t = threadIdx.x;
    for (int idx = t; idx < 2000; idx += 256) {
        int i = idx / 100, j = idx - i * 100;
        A_s[i][j] = fused[(size_t)blk*10000 + (i0 + i)*100 + j] / rden[blk*100 + i0 + i];
    }
    __syncthreads();
    int base = blk * 100;
    float acc[20];
#pragma unroll
    for (int ii = 0; ii < 20; ii++) acc[ii] = 0.f;
    for (int j = 0; j < 100; j++) {
        float vj = v[(size_t)(base + j)*256 + t];
#pragma unroll
        for (int ii = 0; ii < 20; ii++) acc[ii] += A_s[ii][j] * vj;
    }
#pragma unroll
    for (int ii = 0; ii < 20; ii++)
        z[(size_t)(base + i0 + ii)*256 + t] += acc[ii];
}

// ---------------- launcher ----------------
extern "C" void kernel_launch(void* const* d_in, const int* in_sizes, int n_in,
                              void* d_out, int out_size)
{
    const float* x     = (const float*)d_in[0];
    const float* adj   = (const float*)d_in[1];
    const float* Wq_w  = (const float*)d_in[2];
    const float* Wq_b  = (const float*)d_in[3];
    const float* Wk_w  = (const float*)d_in[4];
    const float* Wk_b  = (const float*)d_in[5];
    const float* Wv_w  = (const float*)d_in[6];
    const float* Wv_b  = (const float*)d_in[7];
    const float* Wo_w  = (const float*)d_in[8];
    const float* Wo_b  = (const float*)d_in[9];
    const float* ln_g  = (const float*)d_in[10];
    const float* ln_b  = (const float*)d_in[11];
    const float* fc_w  = (const float*)d_in[12];
    const float* fc_b  = (const float*)d_in[13];
    const float* out_w = (const float*)d_in[14];
    const float* out_b = (const float*)d_in[15];
    const float* proj  = (const float*)d_in[16];
    const float* gum   = (const float*)d_in[17];
    float* out = (float*)d_out;

    float *q, *k, *v, *qp, *kdd, *kdiag, *krmax, *kmax, *kp, *eg, *kvs, *ksum, *winv, *z;
    float *h1p, *wpat, *fused, *rden;
    cudaGetSymbolAddress((void**)&q,     g_q);
    cudaGetSymbolAddress((void**)&k,     g_k);
    cudaGetSymbolAddress((void**)&v,     g_v);
    cudaGetSymbolAddress((void**)&qp,    g_qp);
    cudaGetSymbolAddress((void**)&kdd,   g_kdd);
    cudaGetSymbolAddress((void**)&kdiag, g_kdiag);
    cudaGetSymbolAddress((void**)&krmax, g_krmax);
    cudaGetSymbolAddress((void**)&kmax,  g_kmax);
    cudaGetSymbolAddress((void**)&kp,    g_kp);
    cudaGetSymbolAddress((void**)&eg,    g_eg);
    cudaGetSymbolAddress((void**)&kvs,   g_kvs);
    cudaGetSymbolAddress((void**)&ksum,  g_ksum);
    cudaGetSymbolAddress((void**)&winv,  g_winv);
    cudaGetSymbolAddress((void**)&z,     g_z);
    cudaGetSymbolAddress((void**)&h1p,   g_h1p);
    cudaGetSymbolAddress((void**)&wpat,  g_wpat);
    cudaGetSymbolAddress((void**)&fused, g_fused);
    cudaGetSymbolAddress((void**)&rden,  g_rden);

    // 1) fused Q/K/V projections
    qkv_gemm<<<dim3(BL/128, Dm/128, 3), 256>>>(x, Wq_w, Wk_w, Wv_w,
                                               Wq_b, Wk_b, Wv_b, q, k, v);

    // 2) Performer feature maps
    phi_kernel<<<BL*Hh/16, 256>>>(q, proj, qp, nullptr, nullptr, nullptr, 1);
    phi_kernel<<<BL*Hh/16, 256>>>(k, proj, nullptr, kdd, kdiag, krmax, 0);
    kmax_kernel<<<Bq*Hh, 256>>>(krmax, kmax);
    kp2_kernel<<<(BL*Hh*Mm)/256, 256>>>(kdd, kdiag, kmax, kp);
    eg_kernel<<<(BL*Hh*Kg + 255)/256, 256>>>(gum, eg);

    // 3) ksum, winv, kvs
    ksum_kernel<<<Bq*Hh, 256>>>(kp, eg, ksum);
    winv_kernel<<<Bq*Hh, 256>>>(qp, ksum, winv);
    kvs_kernel<<<Bq*Hh*Kg, 128>>>(kp, v, eg, kvs);

    // 4) z (+fused LayerNorm)
    z_kernel<<<dim3(Bq*Hh, 20), 512>>>(qp, kvs, winv, z, ln_g, ln_b);

    // 5) adjacency patch fusion
    gemm_sk<<<dim3(4, 1, NSPLIT), 256>>>(adj, fc_w, h1p, 512, 128, 10000, KCHUNK);
    score_kernel<<<Bq*Pp, 256>>>(h1p, fc_b, out_w, out_b, wpat);
    fused_kernel<<<(160000 + 255)/256, 256>>>(adj, wpat, fused);
    rden_kernel<<<Bq*Pp*Nn/8, 256>>>(fused, rden);

    // 6) relational bias
    biasadd_kernel<<<dim3(Bq*Pp, 5), 256>>>(fused, rden, v, z);

    // 7) output projection
    gemm_single<<<dim3(BL/128, Dm/128), 256>>>(z, Wo_w, Wo_b, out, Dm, Dm);
}

// round 4
// speedup vs baseline: 2.6017x; 1.0138x over previous
#include <cuda_runtime.h>
#include <math.h>

// ---------------- static problem config ----------------
#define Bq    8
#define Pp    8
#define Nn    100
#define Dm    256
#define Hh    8
#define DKk   32
#define Mm    64
#define Kg    16
#define Ll    800            // P*N
#define BL    6400           // B*L
#define NSPLIT 125
#define KCHUNK 80            // 125*80 = 10000

#define PHI_SCALE 0.84089641525f   // 2 * 32^-0.25

typedef unsigned long long ull;

// ---------------- packed f32x2 helpers ----------------
__device__ __forceinline__ ull pack2(float x, float y) {
    ull r; asm("mov.b64 %0, {%1,%2};" : "=l"(r) : "f"(x), "f"(y)); return r;
}
__device__ __forceinline__ ull fma2(ull a, ull b, ull c) {
    ull d; asm("fma.rn.f32x2 %0, %1, %2, %3;" : "=l"(d) : "l"(a), "l"(b), "l"(c)); return d;
}
__device__ __forceinline__ float2 unpack2(ull p) {
    float2 r; asm("mov.b64 {%0,%1}, %2;" : "=f"(r.x), "=f"(r.y) : "l"(p)); return r;
}

// ---------------- scratch (device globals; no allocation) ----------------
__device__ __align__(16) float g_q   [BL*Dm];
__device__ __align__(16) float g_k   [BL*Dm];
__device__ __align__(16) float g_v   [BL*Dm];
__device__ __align__(16) float g_qp  [BL*Hh*Mm];
__device__ __align__(16) float g_kdd [BL*Hh*Mm];
__device__              float g_kdiag[BL*Hh];
__device__              float g_krmax[BL*Hh];
__device__              float g_kmax [Bq*Hh];
__device__ __align__(16) float g_kp  [BL*Hh*Mm];
__device__ __align__(16) float g_eg  [BL*Hh*Kg];
__device__ __align__(16) float g_kvs [Bq*Hh*Kg*Mm*DKk];
__device__ __align__(16) float g_ksum[Bq*Hh*Kg*Mm];
__device__ __align__(16) float g_winv[BL*Hh*Kg];
__device__ __align__(16) float g_z   [BL*Dm];
__device__ __align__(16) float g_h1p [NSPLIT*512*128];
__device__              float g_wpat [512];
__device__ __align__(16) float g_fused[Bq*Pp*Nn*Nn];
__device__              float g_rden [Bq*Pp*Nn];

// ======== GEMM: 128x128 tile, BK=16, 256 thr, 8x8 micro (FFMA2), dbuf ========
__device__ __forceinline__ void gemm128(const float* __restrict__ A,
                                        const float* __restrict__ W,
                                        const float* __restrict__ bias,
                                        float* __restrict__ C,
                                        int Nc, int Kd, int k0, int klen)
{
    __shared__ __align__(16) float As[2][16][132];
    __shared__ __align__(16) float Ws[2][16][132];
    int tid = threadIdx.x;
    int tx = tid & 15, ty = tid >> 4;
    int row0 = blockIdx.x * 128, col0 = blockIdx.y * 128;
    int lr = tid >> 1, lc = (tid & 1) * 8;

    const float* Ap = A + (size_t)(row0 + lr) * Kd + k0 + lc;
    const float* Wp = W + (size_t)(col0 + lr) * Kd + k0 + lc;

    ull acc[8][4];
#pragma unroll
    for (int i = 0; i < 8; i++)
#pragma unroll
        for (int j = 0; j < 4; j++) acc[i][j] = 0ULL;

    float4 pa0 = *(const float4*)(Ap);
    float4 pa1 = *(const float4*)(Ap + 4);
    float4 pw0 = *(const float4*)(Wp);
    float4 pw1 = *(const float4*)(Wp + 4);

    int nk = klen >> 4;
    int buf = 0;
    for (int it = 0; it < nk; it++) {
        As[buf][lc+0][lr] = pa0.x; As[buf][lc+1][lr] = pa0.y;
        As[buf][lc+2][lr] = pa0.z; As[buf][lc+3][lr] = pa0.w;
        As[buf][lc+4][lr] = pa1.x; As[buf][lc+5][lr] = pa1.y;
        As[buf][lc+6][lr] = pa1.z; As[buf][lc+7][lr] = pa1.w;
        Ws[buf][lc+0][lr] = pw0.x; Ws[buf][lc+1][lr] = pw0.y;
        Ws[buf][lc+2][lr] = pw0.z; Ws[buf][lc+3][lr] = pw0.w;
        Ws[buf][lc+4][lr] = pw1.x; Ws[buf][lc+5][lr] = pw1.y;
        Ws[buf][lc+6][lr] = pw1.z; Ws[buf][lc+7][lr] = pw1.w;
        __syncthreads();
        if (it + 1 < nk) {
            int off = (it + 1) * 16;
            pa0 = *(const float4*)(Ap + off);
            pa1 = *(const float4*)(Ap + off + 4);
            pw0 = *(const float4*)(Wp + off);
            pw1 = *(const float4*)(Wp + off + 4);
        }
#pragma unroll
        for (int c = 0; c < 16; c++) {
            float4 a0 = *(const float4*)&As[buf][c][ty*4];
            float4 a1 = *(const float4*)&As[buf][c][64 + ty*4];
            ulonglong2 w01 = *(const ulonglong2*)&Ws[buf][c][tx*4];
            ulonglong2 w23 = *(const ulonglong2*)&Ws[buf][c][64 + tx*4];
            ull wp[4] = {w01.x, w01.y, w23.x, w23.y};
            float av[8] = {a0.x,a0.y,a0.z,a0.w, a1.x,a1.y,a1.z,a1.w};
#pragma unroll
            for (int i = 0; i < 8; i++) {
                ull ad = pack2(av[i], av[i]);
#pragma unroll
                for (int j = 0; j < 4; j++) acc[i][j] = fma2(ad, wp[j], acc[i][j]);
            }
        }
        buf ^= 1;
        __syncthreads();
    }

    float4 b0 = make_float4(0,0,0,0), b1 = make_float4(0,0,0,0);
    if (bias) {
        b0 = *(const float4*)&bias[col0 + tx*4];
        b1 = *(const float4*)&bias[col0 + 64 + tx*4];
    }
#pragma unroll
    for (int i = 0; i < 8; i++) {
        int rr = row0 + ((i < 4) ? (ty*4 + i) : (64 + ty*4 + i - 4));
        float2 p0 = unpack2(acc[i][0]);
        float2 p1 = unpack2(acc[i][1]);
        float2 p2 = unpack2(acc[i][2]);
        float2 p3 = unpack2(acc[i][3]);
        float4 o0 = make_float4(p0.x+b0.x, p0.y+b0.y, p1.x+b0.z, p1.y+b0.w);
        float4 o1 = make_float4(p2.x+b1.x, p2.y+b1.y, p3.x+b1.z, p3.y+b1.w);
        *(float4*)&C[(size_t)rr * Nc + col0 + tx*4]      = o0;
        *(float4*)&C[(size_t)rr * Nc + col0 + 64 + tx*4] = o1;
    }
}

__global__ void qkv_gemm(const float* __restrict__ A,
                         const float* __restrict__ Wq, const float* __restrict__ Wk,
                         const float* __restrict__ Wv,
                         const float* __restrict__ bq, const float* __restrict__ bk,
                         const float* __restrict__ bv,
                         float* __restrict__ q, float* __restrict__ k, float* __restrict__ v)
{
    const float* W    = blockIdx.z == 0 ? Wq : (blockIdx.z == 1 ? Wk : Wv);
    const float* bias = blockIdx.z == 0 ? bq : (blockIdx.z == 1 ? bk : bv);
    float* C          = blockIdx.z == 0 ? q  : (blockIdx.z == 1 ? k  : v);
    gemm128(A, W, bias, C, Dm, Dm, 0, Dm);
}

__global__ void gemm_single(const float* __restrict__ A, const float* __restrict__ W,
                            const float* __restrict__ bias, float* __restrict__ C,
                            int Nc, int Kd)
{
    gemm128(A, W, bias, C, Nc, Kd, 0, Kd);
}

__global__ void gemm_sk(const float* __restrict__ A, const float* __restrict__ W,
                        float* __restrict__ C, int Mr, int Nc, int Kd, int klen)
{
    gemm128(A, W, nullptr, C + (size_t)blockIdx.z * (size_t)Mr * Nc,
            Nc, Kd, blockIdx.z * klen, klen);
}

// ---------------- Performer feature map (FFMA2) ----------------
__global__ void phi_kernel(const float* __restrict__ din, const float* __restrict__ proj,
                           float* __restrict__ outphi, float* __restrict__ dd_out,
                           float* __restrict__ diag_out, float* __restrict__ rmax_out,
                           int is_query)
{
    __shared__ __align__(16) float proj_s[64][34];
    __shared__ __align__(16) float data_s[4][32];
    __shared__ float wmax[4][2];
    int tid = threadIdx.x;
    for (int i = tid; i < 2048; i += 256) proj_s[i >> 5][i & 31] = proj[i];
    int sub = tid >> 6;
    int m = tid & 63;
    int u0 = blockIdx.x * 16;
    for (int g = 0; g < 16; g += 4) {
        int u = u0 + g + sub;
        __syncthreads();
        if (m < 32) data_s[sub][m] = din[(size_t)u*32 + m] * PHI_SCALE;
        __syncthreads();
        ull dd2 = 0ULL, dg2 = 0ULL;
#pragma unroll
        for (int d2 = 0; d2 < 16; d2++) {
            ull x2 = *(const ull*)&data_s[sub][d2*2];
            ull p2 = *(const ull*)&proj_s[m][d2*2];
            dd2 = fma2(x2, p2, dd2);
            dg2 = fma2(x2, x2, dg2);
        }
        float2 dp = unpack2(dd2);
        float2 gp = unpack2(dg2);
        float dd = dp.x + dp.y;
        float diag = 0.5f * (gp.x + gp.y);
        float mx = dd;
#pragma unroll
        for (int o = 16; o > 0; o >>= 1) mx = fmaxf(mx, __shfl_xor_sync(0xffffffffu, mx, o));
        if ((tid & 31) == 0) wmax[sub][m >> 5] = mx;
        __syncthreads();
        float stab = fmaxf(wmax[sub][0], wmax[sub][1]);
        if (is_query) {
            outphi[(size_t)u*64 + m] = 0.125f * (expf(dd - diag - stab) + 1e-6f);
        } else {
            dd_out[(size_t)u*64 + m] = dd;
            if (m == 0) { diag_out[u] = diag; rmax_out[u] = stab; }
        }
    }
}

__global__ void kmax_kernel(const float* __restrict__ rmax, float* __restrict__ kmax)
{
    int bh = blockIdx.x; int b = bh >> 3, h = bh & 7;
    int t = threadIdx.x;
    __shared__ float red[256];
    float mx = -1e30f;
    for (int l = t; l < Ll; l += 256) mx = fmaxf(mx, rmax[(b*Ll + l)*Hh + h]);
    red[t] = mx; __syncthreads();
    for (int s = 128; s > 0; s >>= 1) { if (t < s) red[t] = fmaxf(red[t], red[t+s]); __syncthreads(); }
    if (t == 0) kmax[bh] = red[0];
}

__global__ void kp2_kernel(const float* __restrict__ dd, const float* __restrict__ diag,
                           const float* __restrict__ kmax, float* __restrict__ kp)
{
    int i = blockIdx.x * 256 + threadIdx.x;
    int u = i >> 6;
    int b = u / (Ll * Hh);
    int h = u & 7;
    kp[i] = 0.125f * (expf(dd[i] - diag[u] - kmax[b*Hh + h]) + 1e-6f);
}

__global__ void eg_kernel(const float* __restrict__ gum, float* __restrict__ eg)
{
    int i = blockIdx.x * 256 + threadIdx.x;
    if (i < BL*Hh*Kg) eg[i] = expf(gum[i]);
}

// ---------------- ksum[bh][k][m] = sum_l kp[l,m] * eg[l,k] ----------------
__global__ void ksum_kernel(const float* __restrict__ kp, const float* __restrict__ eg,
                            float* __restrict__ ksum)
{
    __shared__ __align__(16) float kp_s[16][64];
    __shared__ float eg_s[16][16];
    int bh = blockIdx.x; int b = bh >> 3, h = bh & 7;
    int t = threadIdx.x;
    int lc = t >> 4, lf = t & 15;
    float4 acc = make_float4(0,0,0,0);
    for (int l0 = 0; l0 < Ll; l0 += 16) {
        __syncthreads();
        *(float4*)&kp_s[lc][lf*4] =
            *(const float4*)&kp[((size_t)((b*Ll + l0 + lc)*Hh + h) << 6) + lf*4];
        eg_s[lc][lf] = eg[(((b*Ll + l0 + lc)*Hh + h) << 4) + lf];
        __syncthreads();
#pragma unroll
        for (int c = 0; c < 16; c++) {
            float e = eg_s[c][lc];
            float4 kp4 = *(const float4*)&kp_s[c][lf*4];
            acc.x += kp4.x * e; acc.y += kp4.y * e;
            acc.z += kp4.z * e; acc.w += kp4.w * e;
        }
    }
    *(float4*)&ksum[((size_t)(bh*16 + lc) << 6) + lf*4] = acc;
}

// ---------------- winv[l,k] = 1/((qp . ksum + 1e-8)*16) per bh ----------------
__global__ void winv_kernel(const float* __restrict__ qp, const float* __restrict__ ksum,
                            float* __restrict__ winv)
{
    __shared__ __align__(16) float ks_s[16][64];
    __shared__ __align__(16) float qp_s[16][64];
    int bh = blockIdx.x; int b = bh >> 3, h = bh & 7;
    int t = threadIdx.x;
    int lc = t >> 4, lf = t & 15;
    *(float4*)&ks_s[lc][lf*4] = *(const float4*)&ksum[((size_t)(bh*16 + lc) << 6) + lf*4];
    for (int l0 = 0; l0 < Ll; l0 += 16) {
        __syncthreads();
        *(float4*)&qp_s[lc][lf*4] =
            *(const float4*)&qp[((size_t)((b*Ll + l0 + lc)*Hh + h) << 6) + lf*4];
        __syncthreads();
        ull d2 = 0ULL;
#pragma unroll
        for (int m2 = 0; m2 < 32; m2++) {
            ull q2 = *(const ull*)&qp_s[lc][m2*2];
            ull k2 = *(const ull*)&ks_s[lf][m2*2];
            d2 = fma2(q2, k2, d2);
        }
        float2 dp = unpack2(d2);
        winv[(((b*Ll + l0 + lc)*Hh + h) << 4) + lf] =
            1.0f / ((dp.x + dp.y + 1e-8f) * 16.0f);
    }
}

// ---------------- kvs[bhk][m][d] = sum_l kp[l,m]*eg[l,k]*v[l,d] (FFMA2) -------
__global__ void kvs_kernel(const float* __restrict__ kp, const float* __restrict__ v,
                           const float* __restrict__ eg, float* __restrict__ kvs)
{
    __shared__ __align__(16) float kp_s[16][64];
    __shared__ __align__(16) float v_s[16][32];
    int bhk = blockIdx.x;
    int k = bhk & 15, h = (bhk >> 4) & 7, b = bhk >> 7;
    int t = threadIdx.x;
    int mi = t >> 3, di = t & 7;
    int m0 = mi * 4, d0 = di * 4;
    int lc = t >> 3, lf = t & 7;

    ull accp[4][2];
#pragma unroll
    for (int i = 0; i < 4; i++) { accp[i][0] = 0ULL; accp[i][1] = 0ULL; }

    for (int l0 = 0; l0 < Ll; l0 += 16) {
        __syncthreads();
        size_t ubase = (size_t)((b*Ll + l0 + lc)*Hh + h);
        *(float4*)&kp_s[lc][lf*4]      = *(const float4*)&kp[(ubase << 6) + lf*4];
        *(float4*)&kp_s[lc][lf*4 + 32] = *(const float4*)&kp[(ubase << 6) + lf*4 + 32];
        float e = eg[(ubase << 4) + k];
        float4 v4 = *(const float4*)&v[(size_t)(b*Ll + l0 + lc)*Dm + h*32 + lf*4];
        v4.x *= e; v4.y *= e; v4.z *= e; v4.w *= e;
        *(float4*)&v_s[lc][lf*4] = v4;
        __syncthreads();
#pragma unroll
        for (int c = 0; c < 16; c++) {
            float4 kp4 = *(const float4*)&kp_s[c][m0];
            ulonglong2 vv = *(const ulonglong2*)&v_s[c][d0];
            float a[4] = {kp4.x, kp4.y, kp4.z, kp4.w};
#pragma unroll
            for (int i = 0; i < 4; i++) {
                ull ad = pack2(a[i], a[i]);
                accp[i][0] = fma2(ad, vv.x, accp[i][0]);
                accp[i][1] = fma2(ad, vv.y, accp[i][1]);
            }
        }
    }
    size_t base = (size_t)bhk * 64 * 32;
#pragma unroll
    for (int i = 0; i < 4; i++) {
        float2 p0 = unpack2(accp[i][0]);
        float2 p1 = unpack2(accp[i][1]);
        float4 o = make_float4(p0.x, p0.y, p1.x, p1.y);
        *(float4*)&kvs[base + (size_t)(m0 + i)*32 + d0] = o;
    }
}

// ---------------- z + LayerNorm fused (FFMA2) ----------------
__global__ void z_kernel(const float* __restrict__ qp, const float* __restrict__ kvs,
                         const float* __restrict__ winv, float* __restrict__ z,
                         const float* __restrict__ ln_g, const float* __restrict__ ln_b)
{
    int bh = blockIdx.x; int b = bh >> 3, h = bh & 7;
    int l0 = blockIdx.y * 40;
    int t = threadIdx.x;
    int d = t & 31, k = t >> 5;
    __shared__ __align__(16) float qp_s[4][64];
    __shared__ float wi_s[4][16];
    __shared__ float sred[4][512];

    ull kvp[32];
#pragma unroll
    for (int m2 = 0; m2 < 32; m2++) {
        float lo = kvs[((size_t)(bh*16 + k)*64 + 2*m2    )*32 + d];
        float hi = kvs[((size_t)(bh*16 + k)*64 + 2*m2 + 1)*32 + d];
        kvp[m2] = pack2(lo, hi);
    }

    float gl = 0.f, bl = 0.f;
    if (t < 128) { gl = ln_g[t & 31]; bl = ln_b[t & 31]; }

    for (int li = 0; li < 40; li += 4) {
        __syncthreads();
        if (t < 64) {
            int ti = t >> 4, f = t & 15;
            *(float4*)&qp_s[ti][f*4] =
                *(const float4*)&qp[((size_t)((b*Ll + l0 + li + ti)*Hh + h) << 6) + f*4];
        } else if (t < 128) {
            int tt = t - 64, ti = tt >> 4, kk = tt & 15;
            wi_s[ti][kk] = winv[(((b*Ll + l0 + li + ti)*Hh + h) << 4) + kk];
        }
        __syncthreads();
#pragma unroll
        for (int ti = 0; ti < 4; ti++) {
            ull n0 = 0ULL, n1 = 0ULL;
#pragma unroll
            for (int m2 = 0; m2 < 32; m2 += 2) {
                ulonglong2 q2 = *(const ulonglong2*)&qp_s[ti][m2*2];
                n0 = fma2(q2.x, kvp[m2],     n0);
                n1 = fma2(q2.y, kvp[m2 + 1], n1);
            }
            float2 p0 = unpack2(n0);
            float2 p1 = unpack2(n1);
            sred[ti][t] = (p0.x + p0.y + p1.x + p1.y) * wi_s[ti][k];
        }
        __syncthreads();
        if (t < 128) {
            int ti = t >> 5, d2 = t & 31;
            float ss = 0.f;
#pragma unroll
            for (int kk = 0; kk < 16; kk++) ss += sred[ti][kk*32 + d2];
            float mu = ss;
#pragma unroll
            for (int o = 16; o > 0; o >>= 1) mu += __shfl_xor_sync(0xffffffffu, mu, o);
            mu *= (1.0f / 32.0f);
            float df = ss - mu;
            float v2 = df * df;
#pragma unroll
            for (int o = 16; o > 0; o >>= 1) v2 += __shfl_xor_sync(0xffffffffu, v2, o);
            float var = v2 * (1.0f / 32.0f);
            z[(size_t)(b*Ll + l0 + li + ti)*Dm + h*32 + d2] =
                df * rsqrtf(var + 1e-5f) * gl + bl;
        }
    }
}

// ---------------- patch score + softmax over patch dim ----------------
__global__ void score_kernel(const float* __restrict__ h1p, const float* __restrict__ fc_b,
                             const float* __restrict__ out_w, const float* __restrict__ out_b,
                             float* __restrict__ wout)
{
    int bp = blockIdx.x;
    int t = threadIdx.x >> 5, lane = threadIdx.x & 31;
    __shared__ float sc[8];
    float p = 0.f;
    for (int j = lane; j < 128; j += 32) {
        float hv = fc_b[j];
        for (int s = 0; s < NSPLIT; s++) hv += h1p[(size_t)s*65536 + (bp*8 + t)*128 + j];
        hv = fmaxf(hv, 0.f);
        p += hv * out_w[j];
    }
#pragma unroll
    for (int o = 16; o > 0; o >>= 1) p += __shfl_xor_sync(0xffffffffu, p, o);
    if (lane == 0) sc[t] = p + out_b[0];
    __syncthreads();
    if (threadIdx.x == 0) {
        float mx = sc[0];
#pragma unroll
        for (int i = 1; i < 8; i++) mx = fmaxf(mx, sc[i]);
        float e[8], sum = 0.f;
#pragma unroll
        for (int i = 0; i < 8; i++) { e[i] = expf(sc[i] - mx); sum += e[i]; }
#pragma unroll
        for (int i = 0; i < 8; i++) wout[bp*8 + i] = e[i] / sum;
    }
}

__global__ void fused_kernel(const float* __restrict__ adj, const float* __restrict__ wpat,
                             float* __restrict__ fused)
{
    int i4 = blockIdx.x * 256 + threadIdx.x;    // < 160000
    if (i4 >= 160000) return;
    int bp = i4 / 2500;
    int r4 = i4 - bp * 2500;
    float4 s = make_float4(0,0,0,0);
#pragma unroll
    for (int t = 0; t < 8; t++) {
        float w = wpat[bp*8 + t];
        float4 a = *(const float4*)&adj[(size_t)(bp*8 + t)*10000 + r4*4];
        s.x += a.x*w; s.y += a.y*w; s.z += a.z*w; s.w += a.w*w;
    }
    *(float4*)&fused[(size_t)bp*10000 + r4*4] = s;
}

__global__ void rden_kernel(const float* __restrict__ fused, float* __restrict__ rden)
{
    int w = threadIdx.x >> 5, lane = threadIdx.x & 31;
    int row = blockIdx.x * 8 + w;
    float s = 0.f;
    for (int j = lane; j < 100; j += 32) s += fabsf(fused[(size_t)row*100 + j]);
#pragma unroll
    for (int o = 16; o > 0; o >>= 1) s += __shfl_xor_sync(0xffffffffu, s, o);
    if (lane == 0) rden[row] = fmaxf(s, 1e-12f);
}

// relational bias: z += (fused/rden) @ V (FFMA2); grid (64, 5)
__global__ void biasadd_kernel(const float* __restrict__ fused, const float* __restrict__ rden,
                               const float* __restrict__ v, float* __restrict__ z)
{
    __shared__ __align__(16) float A_s[20][102];
    int blk = blockIdx.x;
    int i0 = blockIdx.y * 20;
    int t = threadIdx.x;
    for (int idx = t; idx < 2000; idx += 256) {
        int i = idx / 100, j = idx - i * 100;
        A_s[i][j] = fused[(size_t)blk*10000 + (i0 + i)*100 + j] / rden[blk*100 + i0 + i];
    }
    __syncthreads();
    int base = blk * 100;
    ull accp[20];
#pragma unroll
    for (int ii = 0; ii < 20; ii++) accp[ii] = 0ULL;
    for (int j = 0; j < 100; j += 2) {
        float vj0 = v[(size_t)(base + j)*256 + t];
        float vj1 = v[(size_t)(base + j + 1)*256 + t];
        ull vp = pack2(vj0, vj1);
#pragma unroll
        for (int ii = 0; ii < 20; ii++)
            accp[ii] = fma2(*(const ull*)&A_s[ii][j], vp, accp[ii]);
    }
#pragma unroll
    for (int ii = 0; ii < 20; ii++) {
        float2 p = unpack2(accp[ii]);
        z[(size_t)(base + i0 + ii)*256 + t] += p.x + p.y;
    }
}

// ---------------- launcher ----------------
extern "C" void kernel_launch(void* const* d_in, const int* in_sizes, int n_in,
                              void* d_out, int out_size)
{
    const float* x     = (const float*)d_in[0];
    const float* adj   = (const float*)d_in[1];
    const float* Wq_w  = (const float*)d_in[2];
    const float* Wq_b  = (const float*)d_in[3];
    const float* Wk_w  = (const float*)d_in[4];
    const float* Wk_b  = (const float*)d_in[5];
    const float* Wv_w  = (const float*)d_in[6];
    const float* Wv_b  = (const float*)d_in[7];
    const float* Wo_w  = (const float*)d_in[8];
    const float* Wo_b  = (const float*)d_in[9];
    const float* ln_g  = (const float*)d_in[10];
    const float* ln_b  = (const float*)d_in[11];
    const float* fc_w  = (const float*)d_in[12];
    const float* fc_b  = (const float*)d_in[13];
    const float* out_w = (const float*)d_in[14];
    const float* out_b = (const float*)d_in[15];
    const float* proj  = (const float*)d_in[16];
    const float* gum   = (const float*)d_in[17];
    float* out = (float*)d_out;

    float *q, *k, *v, *qp, *kdd, *kdiag, *krmax, *kmax, *kp, *eg, *kvs, *ksum, *winv, *z;
    float *h1p, *wpat, *fused, *rden;
    cudaGetSymbolAddress((void**)&q,     g_q);
    cudaGetSymbolAddress((void**)&k,     g_k);
    cudaGetSymbolAddress((void**)&v,     g_v);
    cudaGetSymbolAddress((void**)&qp,    g_qp);
    cudaGetSymbolAddress((void**)&kdd,   g_kdd);
    cudaGetSymbolAddress((void**)&kdiag, g_kdiag);
    cudaGetSymbolAddress((void**)&krmax, g_krmax);
    cudaGetSymbolAddress((void**)&kmax,  g_kmax);
    cudaGetSymbolAddress((void**)&kp,    g_kp);
    cudaGetSymbolAddress((void**)&eg,    g_eg);
    cudaGetSymbolAddress((void**)&kvs,   g_kvs);
    cudaGetSymbolAddress((void**)&ksum,  g_ksum);
    cudaGetSymbolAddress((void**)&winv,  g_winv);
    cudaGetSymbolAddress((void**)&z,     g_z);
    cudaGetSymbolAddress((void**)&h1p,   g_h1p);
    cudaGetSymbolAddress((void**)&wpat,  g_wpat);
    cudaGetSymbolAddress((void**)&fused, g_fused);
    cudaGetSymbolAddress((void**)&rden,  g_rden);

    // 1) fused Q/K/V projections
    qkv_gemm<<<dim3(BL/128, Dm/128, 3), 256>>>(x, Wq_w, Wk_w, Wv_w,
                                               Wq_b, Wk_b, Wv_b, q, k, v);

    // 2) Performer feature maps
    phi_kernel<<<BL*Hh/16, 256>>>(q, proj, qp, nullptr, nullptr, nullptr, 1);
    phi_kernel<<<BL*Hh/16, 256>>>(k, proj, nullptr, kdd, kdiag, krmax, 0);
    kmax_kernel<<<Bq*Hh, 256>>>(krmax, kmax);
    kp2_kernel<<<(BL*Hh*Mm)/256, 256>>>(kdd, kdiag, kmax, kp);
    eg_kernel<<<(BL*Hh*Kg + 255)/256, 256>>>(gum, eg);

    // 3) ksum, winv, kvs
    ksum_kernel<<<Bq*Hh, 256>>>(kp, eg, ksum);
    winv_kernel<<<Bq*Hh, 256>>>(qp, ksum, winv);
    kvs_kernel<<<Bq*Hh*Kg, 128>>>(kp, v, eg, kvs);

    // 4) z (+fused LayerNorm)
    z_kernel<<<dim3(Bq*Hh, 20), 512>>>(qp, kvs, winv, z, ln_g, ln_b);

    // 5) adjacency patch fusion (125-way split-K)
    gemm_sk<<<dim3(4, 1, NSPLIT), 256>>>(adj, fc_w, h1p, 512, 128, 10000, KCHUNK);
    score_kernel<<<Bq*Pp, 256>>>(h1p, fc_b, out_w, out_b, wpat);
    fused_kernel<<<(160000 + 255)/256, 256>>>(adj, wpat, fused);
    rden_kernel<<<Bq*Pp*Nn/8, 256>>>(fused, rden);

    // 6) relational bias
    biasadd_kernel<<<dim3(Bq*Pp, 5), 256>>>(fused, rden, v, z);

    // 7) output projection
    gemm_single<<<dim3(BL/128, Dm/128), 256>>>(z, Wo_w, Wo_b, out, Dm, Dm);
}